// round 1
// baseline (speedup 1.0000x reference)
#include <cuda_runtime.h>
#include <cuda_bf16.h>
#include <cstdint>

// Problem constants
#define LSEQ 8192
#define FIN  1024
#define CDIM 256
#define C3   768
#define NH   8
#define DH   32
#define KS   63

// Scratch (static device allocs are permitted)
__device__ float g_y[LSEQ * CDIM];      // 8 MB
__device__ float g_qkv[LSEQ * C3];      // 24 MB
__device__ float g_att[LSEQ * CDIM];    // 8 MB

// ---------------------------------------------------------------------------
// Register-tiled SGEMM: C[M,N] = A[M,K] @ B[K,N] + bias[N]
// BM=128, BN=64, BK=16, 256 threads, each thread 8x4.
// M % 128 == 0, N % 64 == 0, K % 16 == 0 (all true for our shapes).
// ---------------------------------------------------------------------------
__global__ __launch_bounds__(256) void sgemm_bias_kernel(
    const float* __restrict__ A, const float* __restrict__ B,
    const float* __restrict__ bias, float* __restrict__ C,
    int M, int N, int K)
{
    constexpr int BM = 128, BN = 64, BK = 16;
    __shared__ float As[BK][BM];   // transposed: As[k][m]
    __shared__ float Bs[BK][BN];

    const int bm = blockIdx.y * BM;
    const int bn = blockIdx.x * BN;
    const int tid = threadIdx.x;
    const int tx = tid & 15;        // 0..15 -> N
    const int ty = tid >> 4;        // 0..15 -> M

    float acc[8][4];
    #pragma unroll
    for (int i = 0; i < 8; i++)
        #pragma unroll
        for (int j = 0; j < 4; j++) acc[i][j] = 0.f;

    for (int k0 = 0; k0 < K; k0 += BK) {
        // Load A tile: 128x16 = 512 float4, 2 per thread
        #pragma unroll
        for (int it = 0; it < 2; it++) {
            int gid = tid + it * 256;
            int row = gid >> 2;
            int c4  = (gid & 3) * 4;
            float4 a = *(const float4*)&A[(size_t)(bm + row) * K + k0 + c4];
            As[c4 + 0][row] = a.x;
            As[c4 + 1][row] = a.y;
            As[c4 + 2][row] = a.z;
            As[c4 + 3][row] = a.w;
        }
        // Load B tile: 16x64 = 256 float4, 1 per thread
        {
            int br = tid >> 4;
            int bc = (tid & 15) * 4;
            float4 b = *(const float4*)&B[(size_t)(k0 + br) * N + bn + bc];
            *(float4*)&Bs[br][bc] = b;
        }
        __syncthreads();

        #pragma unroll
        for (int kk = 0; kk < BK; kk++) {
            float ar[8], brg[4];
            #pragma unroll
            for (int i = 0; i < 8; i++) ar[i] = As[kk][ty * 8 + i];
            #pragma unroll
            for (int j = 0; j < 4; j++) brg[j] = Bs[kk][tx * 4 + j];
            #pragma unroll
            for (int i = 0; i < 8; i++)
                #pragma unroll
                for (int j = 0; j < 4; j++)
                    acc[i][j] = fmaf(ar[i], brg[j], acc[i][j]);
        }
        __syncthreads();
    }

    float4 b4 = *(const float4*)&bias[bn + tx * 4];
    #pragma unroll
    for (int i = 0; i < 8; i++) {
        int r = bm + ty * 8 + i;
        float4 o;
        o.x = acc[i][0] + b4.x;
        o.y = acc[i][1] + b4.y;
        o.z = acc[i][2] + b4.z;
        o.w = acc[i][3] + b4.w;
        *(float4*)&C[(size_t)r * N + bn + tx * 4] = o;
    }
}

// ---------------------------------------------------------------------------
// NATTEN-1D attention. One block per sequence position l (8192 blocks),
// 8 warps, warp h handles head h. d=32 -> one element per lane.
// Window: start = clip(l-31, 0, L-63), 63 keys.
// ---------------------------------------------------------------------------
__global__ __launch_bounds__(256) void natten_kernel(
    const float* __restrict__ qkv, float* __restrict__ out)
{
    const int l = blockIdx.x;
    const int h = threadIdx.x >> 5;
    const int lane = threadIdx.x & 31;

    int start = l - 31;
    if (start < 0) start = 0;
    if (start > LSEQ - KS) start = LSEQ - KS;

    const float scale = 0.17677669529663687f;  // 32^-0.5
    const float q = qkv[(size_t)l * C3 + h * DH + lane] * scale;

    float s0 = 0.f, s1 = 0.f;

    const float* kbase = qkv + (size_t)start * C3 + CDIM + h * DH + lane;
    #pragma unroll 1
    for (int j = 0; j < KS; j++) {
        float p = q * kbase[(size_t)j * C3];
        #pragma unroll
        for (int o = 16; o > 0; o >>= 1)
            p += __shfl_xor_sync(0xffffffffu, p, o);
        if (j < 32) { if (j == lane) s0 = p; }
        else        { if ((j - 32) == lane) s1 = p; }
    }

    float m = fmaxf(s0, (lane < 31) ? s1 : -1e30f);
    #pragma unroll
    for (int o = 16; o > 0; o >>= 1)
        m = fmaxf(m, __shfl_xor_sync(0xffffffffu, m, o));

    float e0 = __expf(s0 - m);
    float e1 = (lane < 31) ? __expf(s1 - m) : 0.f;
    float sum = e0 + e1;
    #pragma unroll
    for (int o = 16; o > 0; o >>= 1)
        sum += __shfl_xor_sync(0xffffffffu, sum, o);
    float inv = __frcp_rn(sum);
    float p0 = e0 * inv;
    float p1 = e1 * inv;

    float acc = 0.f;
    const float* vbase = qkv + (size_t)start * C3 + 2 * CDIM + h * DH + lane;
    #pragma unroll 1
    for (int j = 0; j < KS; j++) {
        float pj = __shfl_sync(0xffffffffu, (j < 32) ? p0 : p1, j & 31);
        acc = fmaf(pj, vbase[(size_t)j * C3], acc);
    }

    out[(size_t)l * CDIM + h * DH + lane] = acc;
}

// ---------------------------------------------------------------------------
extern "C" void kernel_launch(void* const* d_in, const int* in_sizes, int n_in,
                              void* d_out, int out_size)
{
    const float* x    = (const float*)d_in[0];  // [8192,1024]
    const float* Wp   = (const float*)d_in[1];  // [1024,256]
    const float* bp   = (const float*)d_in[2];  // [256]
    const float* Wqkv = (const float*)d_in[3];  // [256,768]
    const float* bqkv = (const float*)d_in[4];  // [768]
    const float* Wo   = (const float*)d_in[5];  // [256,256]
    const float* bo   = (const float*)d_in[6];  // [256]
    float* out = (float*)d_out;                 // [8192,256]

    float *p_y, *p_qkv, *p_att;
    cudaGetSymbolAddress((void**)&p_y,   g_y);
    cudaGetSymbolAddress((void**)&p_qkv, g_qkv);
    cudaGetSymbolAddress((void**)&p_att, g_att);

    // y = x @ Wp + bp   [8192,1024]x[1024,256]
    sgemm_bias_kernel<<<dim3(CDIM / 64, LSEQ / 128), 256>>>(
        x, Wp, bp, p_y, LSEQ, CDIM, FIN);

    // qkv = y @ Wqkv + bqkv   [8192,256]x[256,768]
    sgemm_bias_kernel<<<dim3(C3 / 64, LSEQ / 128), 256>>>(
        p_y, Wqkv, bqkv, p_qkv, LSEQ, C3, CDIM);

    // attention
    natten_kernel<<<LSEQ, 256>>>(p_qkv, p_att);

    // out = att @ Wo + bo   [8192,256]x[256,256]
    sgemm_bias_kernel<<<dim3(CDIM / 64, LSEQ / 128), 256>>>(
        p_att, Wo, bo, out, LSEQ, CDIM, CDIM);
}

// round 3
// speedup vs baseline: 2.0079x; 2.0079x over previous
#include <cuda_runtime.h>
#include <cuda_bf16.h>
#include <cstdint>

#define LSEQ 8192
#define FIN  1024
#define CDIM 256
#define C3   768
#define NH   8
#define DH   32
#define KS   63

__device__ float g_y[LSEQ * CDIM];
__device__ float g_qkv[LSEQ * C3];
__device__ float g_att[LSEQ * CDIM];

// ---------------------------------------------------------------------------
// 3xTF32 tensor-core GEMM: C[M,N] = A[M,K] @ B[K,N] + bias
// BM=128 BN=64 BK=16, 256 thr (8 warps, 4x2), warp tile 32x32 via m16n8k8.
// Each operand split hi/lo; D += Ah*Bh + Ah*Bl + Al*Bh  (fp32-level accuracy).
// ---------------------------------------------------------------------------
#define ASTRIDE 20
#define BSTRIDE 72

__device__ __forceinline__ void cp16(void* smem, const void* g) {
    uint32_t s = (uint32_t)__cvta_generic_to_shared(smem);
    asm volatile("cp.async.cg.shared.global [%0], [%1], 16;\n" :: "r"(s), "l"(g));
}
__device__ __forceinline__ void cp_commit() {
    asm volatile("cp.async.commit_group;\n");
}

__device__ __forceinline__ void mma_tf32(float* d, const uint32_t* a, const uint32_t* b) {
    asm volatile(
        "mma.sync.aligned.m16n8k8.row.col.f32.tf32.tf32.f32 "
        "{%0,%1,%2,%3}, {%4,%5,%6,%7}, {%8,%9}, {%0,%1,%2,%3};\n"
        : "+f"(d[0]), "+f"(d[1]), "+f"(d[2]), "+f"(d[3])
        : "r"(a[0]), "r"(a[1]), "r"(a[2]), "r"(a[3]), "r"(b[0]), "r"(b[1]));
}

__device__ __forceinline__ void split_tf32(float x, uint32_t& hi, uint32_t& lo) {
    uint32_t h = __float_as_uint(x) & 0xffffe000u;
    hi = h;
    lo = __float_as_uint(x - __uint_as_float(h));
}

__global__ __launch_bounds__(256) void gemm_tf32_kernel(
    const float* __restrict__ A, const float* __restrict__ B,
    const float* __restrict__ bias, float* __restrict__ C,
    int M, int N, int K)
{
    __shared__ float As[2][128 * ASTRIDE];
    __shared__ float Bs[2][16 * BSTRIDE];

    const int bm = blockIdx.y * 128;
    const int bn = blockIdx.x * 64;
    const int tid = threadIdx.x;
    const int wid = tid >> 5;
    const int lane = tid & 31;
    const int warp_m = wid & 3;
    const int warp_n = wid >> 2;
    const int r = lane >> 2;
    const int c = lane & 3;

    const int arow0 = tid >> 2;
    const int ac4   = (tid & 3) * 4;
    const int brow  = tid >> 4;
    const int bc4   = (tid & 15) * 4;

    float acc[2][4][4];
    #pragma unroll
    for (int i = 0; i < 2; i++)
        #pragma unroll
        for (int j = 0; j < 4; j++)
            #pragma unroll
            for (int e = 0; e < 4; e++) acc[i][j][e] = 0.f;

    const int T = K >> 4;

    {
        cp16(&As[0][arow0 * ASTRIDE + ac4], &A[(size_t)(bm + arow0) * K + ac4]);
        cp16(&As[0][(arow0 + 64) * ASTRIDE + ac4], &A[(size_t)(bm + arow0 + 64) * K + ac4]);
        cp16(&Bs[0][brow * BSTRIDE + bc4], &B[(size_t)brow * N + bn + bc4]);
        cp_commit();
    }

    for (int kt = 0; kt < T; kt++) {
        const int buf = kt & 1;
        if (kt + 1 < T) {
            const int k0 = (kt + 1) << 4;
            const int nb = buf ^ 1;
            cp16(&As[nb][arow0 * ASTRIDE + ac4], &A[(size_t)(bm + arow0) * K + k0 + ac4]);
            cp16(&As[nb][(arow0 + 64) * ASTRIDE + ac4], &A[(size_t)(bm + arow0 + 64) * K + k0 + ac4]);
            cp16(&Bs[nb][brow * BSTRIDE + bc4], &B[(size_t)(k0 + brow) * N + bn + bc4]);
            cp_commit();
            asm volatile("cp.async.wait_group 1;\n");
        } else {
            asm volatile("cp.async.wait_group 0;\n");
        }
        __syncthreads();

        const float* as = As[buf];
        const float* bs = Bs[buf];
        #pragma unroll
        for (int ks = 0; ks < 16; ks += 8) {
            uint32_t afh[2][4], afl[2][4], bfh[4][2], bfl[4][2];
            #pragma unroll
            for (int mi = 0; mi < 2; mi++) {
                int m0 = warp_m * 32 + mi * 16;
                split_tf32(as[(m0 + r)     * ASTRIDE + ks + c],     afh[mi][0], afl[mi][0]);
                split_tf32(as[(m0 + r + 8) * ASTRIDE + ks + c],     afh[mi][1], afl[mi][1]);
                split_tf32(as[(m0 + r)     * ASTRIDE + ks + c + 4], afh[mi][2], afl[mi][2]);
                split_tf32(as[(m0 + r + 8) * ASTRIDE + ks + c + 4], afh[mi][3], afl[mi][3]);
            }
            #pragma unroll
            for (int nj = 0; nj < 4; nj++) {
                int n0 = warp_n * 32 + nj * 8 + r;
                split_tf32(bs[(ks + c)     * BSTRIDE + n0], bfh[nj][0], bfl[nj][0]);
                split_tf32(bs[(ks + c + 4) * BSTRIDE + n0], bfh[nj][1], bfl[nj][1]);
            }
            #pragma unroll
            for (int mi = 0; mi < 2; mi++)
                #pragma unroll
                for (int nj = 0; nj < 4; nj++) {
                    mma_tf32(acc[mi][nj], afl[mi], bfh[nj]);
                    mma_tf32(acc[mi][nj], afh[mi], bfl[nj]);
                    mma_tf32(acc[mi][nj], afh[mi], bfh[nj]);
                }
        }
        __syncthreads();
    }

    #pragma unroll
    for (int mi = 0; mi < 2; mi++) {
        #pragma unroll
        for (int nj = 0; nj < 4; nj++) {
            int row = bm + warp_m * 32 + mi * 16 + r;
            int col = bn + warp_n * 32 + nj * 8 + c * 2;
            float2 bb = *(const float2*)&bias[col];
            float2 o0, o1;
            o0.x = acc[mi][nj][0] + bb.x;
            o0.y = acc[mi][nj][1] + bb.y;
            o1.x = acc[mi][nj][2] + bb.x;
            o1.y = acc[mi][nj][3] + bb.y;
            *(float2*)&C[(size_t)row * N + col] = o0;
            *(float2*)&C[(size_t)(row + 8) * N + col] = o1;
        }
    }
}

// ---------------------------------------------------------------------------
// NATTEN-1D, smem-tiled. Block = (64 queries, 1 head). 256 threads = 8 warps,
// each warp handles 8 queries. K/V window (126 rows x 32) staged in smem.
// ---------------------------------------------------------------------------
#define TQ 64
#define KV 126
#define RS 36

__global__ __launch_bounds__(256) void natten_kernel(
    const float* __restrict__ qkv, float* __restrict__ out)
{
    __shared__ float Ks[(KV + 1) * RS];
    __shared__ float Vs[(KV + 1) * RS];
    __shared__ float Qs[TQ * RS];

    const int t0 = blockIdx.x * TQ;
    const int h = blockIdx.y;
    const int tid = threadIdx.x;
    const int w = tid >> 5;
    const int lane = tid & 31;

    int base = t0 - 31;
    if (base < 0) base = 0;
    if (base > LSEQ - KV) base = LSEQ - KV;

    const float scale = 0.17677669529663687f;

    for (int idx = tid; idx < KV * 32; idx += 256) {
        int row = idx >> 5;
        int d = idx & 31;
        size_t g = (size_t)(base + row) * C3 + CDIM + h * DH + d;
        Ks[row * RS + d] = qkv[g];
        Vs[row * RS + d] = qkv[g + CDIM];
    }
    for (int idx = tid; idx < TQ * 32; idx += 256) {
        int row = idx >> 5;
        int d = idx & 31;
        Qs[row * RS + d] = qkv[(size_t)(t0 + row) * C3 + h * DH + d] * scale;
    }
    __syncthreads();

    #pragma unroll 1
    for (int qi = 0; qi < 8; qi++) {
        const int lq = w * 8 + qi;
        const int l = t0 + lq;
        int start = l - 31;
        if (start < 0) start = 0;
        if (start > LSEQ - KS) start = LSEQ - KS;
        const int ws = start - base;

        const float4* k0p = (const float4*)&Ks[(ws + lane) * RS];
        const float4* k1p = (const float4*)&Ks[(ws + 32 + lane) * RS];
        const float4* qp  = (const float4*)&Qs[lq * RS];

        float s0 = 0.f, s1 = 0.f;
        #pragma unroll
        for (int d4 = 0; d4 < 8; d4++) {
            float4 q4 = qp[d4];
            float4 ka = k0p[d4];
            float4 kb = k1p[d4];
            s0 += q4.x * ka.x + q4.y * ka.y + q4.z * ka.z + q4.w * ka.w;
            s1 += q4.x * kb.x + q4.y * kb.y + q4.z * kb.z + q4.w * kb.w;
        }

        float m = fmaxf(s0, (lane < 31) ? s1 : -1e30f);
        #pragma unroll
        for (int o = 16; o > 0; o >>= 1)
            m = fmaxf(m, __shfl_xor_sync(0xffffffffu, m, o));
        float e0 = __expf(s0 - m);
        float e1 = (lane < 31) ? __expf(s1 - m) : 0.f;
        float sum = e0 + e1;
        #pragma unroll
        for (int o = 16; o > 0; o >>= 1)
            sum += __shfl_xor_sync(0xffffffffu, sum, o);
        float inv = __frcp_rn(sum);
        float p0 = e0 * inv;
        float p1 = e1 * inv;

        float acc = 0.f;
        const float* vb = &Vs[ws * RS + lane];
        #pragma unroll
        for (int j = 0; j < KS; j++) {
            float pj = __shfl_sync(0xffffffffu, (j < 32) ? p0 : p1, j & 31);
            acc = fmaf(pj, vb[j * RS], acc);
        }

        out[(size_t)l * CDIM + h * DH + lane] = acc;
    }
}

// ---------------------------------------------------------------------------
extern "C" void kernel_launch(void* const* d_in, const int* in_sizes, int n_in,
                              void* d_out, int out_size)
{
    const float* x    = (const float*)d_in[0];
    const float* Wp   = (const float*)d_in[1];
    const float* bp   = (const float*)d_in[2];
    const float* Wqkv = (const float*)d_in[3];
    const float* bqkv = (const float*)d_in[4];
    const float* Wo   = (const float*)d_in[5];
    const float* bo   = (const float*)d_in[6];
    float* out = (float*)d_out;

    float *p_y, *p_qkv, *p_att;
    cudaGetSymbolAddress((void**)&p_y,   g_y);
    cudaGetSymbolAddress((void**)&p_qkv, g_qkv);
    cudaGetSymbolAddress((void**)&p_att, g_att);

    gemm_tf32_kernel<<<dim3(CDIM / 64, LSEQ / 128), 256>>>(
        x, Wp, bp, p_y, LSEQ, CDIM, FIN);

    gemm_tf32_kernel<<<dim3(C3 / 64, LSEQ / 128), 256>>>(
        p_y, Wqkv, bqkv, p_qkv, LSEQ, C3, CDIM);

    natten_kernel<<<dim3(LSEQ / TQ, NH), 256>>>(p_qkv, p_att);

    gemm_tf32_kernel<<<dim3(CDIM / 64, LSEQ / 128), 256>>>(
        p_att, Wo, bo, out, LSEQ, CDIM, CDIM);
}

// round 4
// speedup vs baseline: 2.0525x; 1.0222x over previous
#include <cuda_runtime.h>
#include <cuda_bf16.h>
#include <cstdint>

#define LSEQ 8192
#define FIN  1024
#define CDIM 256
#define C3   768
#define NH   8
#define DH   32
#define KS   63

__device__ float g_y[LSEQ * CDIM];
__device__ float g_qkv[LSEQ * C3];
__device__ float g_att[LSEQ * CDIM];

// ---------------------------------------------------------------------------
// 3xTF32 tensor-core GEMM (unchanged from round 3): C = A@B + bias
// ---------------------------------------------------------------------------
#define ASTRIDE 20
#define BSTRIDE 72

__device__ __forceinline__ void cp16(void* smem, const void* g) {
    uint32_t s = (uint32_t)__cvta_generic_to_shared(smem);
    asm volatile("cp.async.cg.shared.global [%0], [%1], 16;\n" :: "r"(s), "l"(g));
}
__device__ __forceinline__ void cp_commit() {
    asm volatile("cp.async.commit_group;\n");
}

__device__ __forceinline__ void mma_tf32(float* d, const uint32_t* a, const uint32_t* b) {
    asm volatile(
        "mma.sync.aligned.m16n8k8.row.col.f32.tf32.tf32.f32 "
        "{%0,%1,%2,%3}, {%4,%5,%6,%7}, {%8,%9}, {%0,%1,%2,%3};\n"
        : "+f"(d[0]), "+f"(d[1]), "+f"(d[2]), "+f"(d[3])
        : "r"(a[0]), "r"(a[1]), "r"(a[2]), "r"(a[3]), "r"(b[0]), "r"(b[1]));
}

__device__ __forceinline__ void split_tf32(float x, uint32_t& hi, uint32_t& lo) {
    uint32_t h = __float_as_uint(x) & 0xffffe000u;
    hi = h;
    lo = __float_as_uint(x - __uint_as_float(h));
}

__global__ __launch_bounds__(256) void gemm_tf32_kernel(
    const float* __restrict__ A, const float* __restrict__ B,
    const float* __restrict__ bias, float* __restrict__ C,
    int M, int N, int K)
{
    __shared__ float As[2][128 * ASTRIDE];
    __shared__ float Bs[2][16 * BSTRIDE];

    const int bm = blockIdx.y * 128;
    const int bn = blockIdx.x * 64;
    const int tid = threadIdx.x;
    const int wid = tid >> 5;
    const int lane = tid & 31;
    const int warp_m = wid & 3;
    const int warp_n = wid >> 2;
    const int r = lane >> 2;
    const int c = lane & 3;

    const int arow0 = tid >> 2;
    const int ac4   = (tid & 3) * 4;
    const int brow  = tid >> 4;
    const int bc4   = (tid & 15) * 4;

    float acc[2][4][4];
    #pragma unroll
    for (int i = 0; i < 2; i++)
        #pragma unroll
        for (int j = 0; j < 4; j++)
            #pragma unroll
            for (int e = 0; e < 4; e++) acc[i][j][e] = 0.f;

    const int T = K >> 4;

    {
        cp16(&As[0][arow0 * ASTRIDE + ac4], &A[(size_t)(bm + arow0) * K + ac4]);
        cp16(&As[0][(arow0 + 64) * ASTRIDE + ac4], &A[(size_t)(bm + arow0 + 64) * K + ac4]);
        cp16(&Bs[0][brow * BSTRIDE + bc4], &B[(size_t)brow * N + bn + bc4]);
        cp_commit();
    }

    for (int kt = 0; kt < T; kt++) {
        const int buf = kt & 1;
        if (kt + 1 < T) {
            const int k0 = (kt + 1) << 4;
            const int nb = buf ^ 1;
            cp16(&As[nb][arow0 * ASTRIDE + ac4], &A[(size_t)(bm + arow0) * K + k0 + ac4]);
            cp16(&As[nb][(arow0 + 64) * ASTRIDE + ac4], &A[(size_t)(bm + arow0 + 64) * K + k0 + ac4]);
            cp16(&Bs[nb][brow * BSTRIDE + bc4], &B[(size_t)(k0 + brow) * N + bn + bc4]);
            cp_commit();
            asm volatile("cp.async.wait_group 1;\n");
        } else {
            asm volatile("cp.async.wait_group 0;\n");
        }
        __syncthreads();

        const float* as = As[buf];
        const float* bs = Bs[buf];
        #pragma unroll
        for (int ks = 0; ks < 16; ks += 8) {
            uint32_t afh[2][4], afl[2][4], bfh[4][2], bfl[4][2];
            #pragma unroll
            for (int mi = 0; mi < 2; mi++) {
                int m0 = warp_m * 32 + mi * 16;
                split_tf32(as[(m0 + r)     * ASTRIDE + ks + c],     afh[mi][0], afl[mi][0]);
                split_tf32(as[(m0 + r + 8) * ASTRIDE + ks + c],     afh[mi][1], afl[mi][1]);
                split_tf32(as[(m0 + r)     * ASTRIDE + ks + c + 4], afh[mi][2], afl[mi][2]);
                split_tf32(as[(m0 + r + 8) * ASTRIDE + ks + c + 4], afh[mi][3], afl[mi][3]);
            }
            #pragma unroll
            for (int nj = 0; nj < 4; nj++) {
                int n0 = warp_n * 32 + nj * 8 + r;
                split_tf32(bs[(ks + c)     * BSTRIDE + n0], bfh[nj][0], bfl[nj][0]);
                split_tf32(bs[(ks + c + 4) * BSTRIDE + n0], bfh[nj][1], bfl[nj][1]);
            }
            #pragma unroll
            for (int mi = 0; mi < 2; mi++)
                #pragma unroll
                for (int nj = 0; nj < 4; nj++) {
                    mma_tf32(acc[mi][nj], afl[mi], bfh[nj]);
                    mma_tf32(acc[mi][nj], afh[mi], bfl[nj]);
                    mma_tf32(acc[mi][nj], afh[mi], bfh[nj]);
                }
        }
        __syncthreads();
    }

    #pragma unroll
    for (int mi = 0; mi < 2; mi++) {
        #pragma unroll
        for (int nj = 0; nj < 4; nj++) {
            int row = bm + warp_m * 32 + mi * 16 + r;
            int col = bn + warp_n * 32 + nj * 8 + c * 2;
            float2 bb = *(const float2*)&bias[col];
            float2 o0, o1;
            o0.x = acc[mi][nj][0] + bb.x;
            o0.y = acc[mi][nj][1] + bb.y;
            o1.x = acc[mi][nj][2] + bb.x;
            o1.y = acc[mi][nj][3] + bb.y;
            *(float2*)&C[(size_t)row * N + col] = o0;
            *(float2*)&C[(size_t)(row + 8) * N + col] = o1;
        }
    }
}

// ---------------------------------------------------------------------------
// NATTEN-1D v2: per-warp transposed-P smem tile; shfl-free P·V union loop.
// Block = (64 queries, 1 head), 8 warps x 8 queries. Dynamic smem ~73 KB.
// ---------------------------------------------------------------------------
#define TQ 64
#define KV 126     // staged rows; row 126 zeroed
#define RS 36      // K/V/Q row stride (floats)
#define PTS 12     // Pt row stride (floats, 16B-aligned rows)
#define PTROWS 72  // per-warp Pt rows (union <= 71)

__device__ __forceinline__ int win_start(int l) {
    int s = l - 31;
    if (s < 0) s = 0;
    if (s > LSEQ - KS) s = LSEQ - KS;
    return s;
}

__global__ __launch_bounds__(256) void natten_kernel(
    const float* __restrict__ qkv, float* __restrict__ out)
{
    extern __shared__ float sm[];
    float* Ks = sm;                         // 127*RS
    float* Vs = Ks + 127 * RS;              // 127*RS
    float* Qs = Vs + 127 * RS;              // 64*RS
    float* Pt = Qs + TQ * RS;               // 8 * PTROWS * PTS

    const int t0 = blockIdx.x * TQ;
    const int h = blockIdx.y;
    const int tid = threadIdx.x;
    const int w = tid >> 5;
    const int lane = tid & 31;

    int base = t0 - 31;
    if (base < 0) base = 0;
    if (base > LSEQ - KV) base = LSEQ - KV;

    const float scale = 0.17677669529663687f;

    // stage K,V rows 0..125
    for (int idx = tid; idx < KV * 32; idx += 256) {
        int row = idx >> 5;
        int d = idx & 31;
        size_t g = (size_t)(base + row) * C3 + CDIM + h * DH + d;
        Ks[row * RS + d] = qkv[g];
        Vs[row * RS + d] = qkv[g + CDIM];
    }
    if (tid < 32) {                 // zero pad row 126
        Ks[126 * RS + tid] = 0.f;
        Vs[126 * RS + tid] = 0.f;
    }
    // stage Q (pre-scaled)
    for (int idx = tid; idx < TQ * 32; idx += 256) {
        int row = idx >> 5;
        int d = idx & 31;
        Qs[row * RS + d] = qkv[(size_t)(t0 + row) * C3 + h * DH + d] * scale;
    }
    // zero Pt
    for (int idx = tid; idx < 8 * PTROWS * PTS; idx += 256)
        Pt[idx] = 0.f;
    __syncthreads();

    const int l0 = t0 + w * 8;
    const int ws0 = win_start(l0) - base;
    const int ws7 = win_start(l0 + 7) - base;
    float* Ptw = Pt + w * PTROWS * PTS;

    // Phase A: scores + softmax per query; write transposed P
    #pragma unroll 1
    for (int qi = 0; qi < 8; qi++) {
        const int lq = w * 8 + qi;
        const int l = t0 + lq;
        const int ws = win_start(l) - base;

        const float4* k0p = (const float4*)&Ks[(ws + lane) * RS];
        const float4* k1p = (const float4*)&Ks[(ws + 32 + lane) * RS];
        const float4* qp  = (const float4*)&Qs[lq * RS];

        float s0 = 0.f, s1 = 0.f;
        #pragma unroll
        for (int d4 = 0; d4 < 8; d4++) {
            float4 q4 = qp[d4];
            float4 ka = k0p[d4];
            float4 kb = k1p[d4];
            s0 += q4.x * ka.x + q4.y * ka.y + q4.z * ka.z + q4.w * ka.w;
            s1 += q4.x * kb.x + q4.y * kb.y + q4.z * kb.z + q4.w * kb.w;
        }

        float m = fmaxf(s0, (lane < 31) ? s1 : -1e30f);
        #pragma unroll
        for (int o = 16; o > 0; o >>= 1)
            m = fmaxf(m, __shfl_xor_sync(0xffffffffu, m, o));
        float e0 = __expf(s0 - m);
        float e1 = (lane < 31) ? __expf(s1 - m) : 0.f;
        float sum = e0 + e1;
        #pragma unroll
        for (int o = 16; o > 0; o >>= 1)
            sum += __shfl_xor_sync(0xffffffffu, sum, o);
        float inv = __frcp_rn(sum);

        const int off = ws - ws0;  // 0..7
        Ptw[(off + lane) * PTS + qi]      = e0 * inv;
        Ptw[(off + 32 + lane) * PTS + qi] = e1 * inv;   // lane31 writes 0
    }
    __syncwarp();

    // Phase B: union loop over warp's key-row span; lane = output dim
    const int nU = ws7 - ws0 + 64;       // <= 71
    float acc[8];
    #pragma unroll
    for (int q = 0; q < 8; q++) acc[q] = 0.f;

    const float* vb = &Vs[ws0 * RS + lane];
    #pragma unroll 4
    for (int jj = 0; jj < nU; jj++) {
        float v = vb[jj * RS];
        float4 pa = *(const float4*)&Ptw[jj * PTS];
        float4 pb = *(const float4*)&Ptw[jj * PTS + 4];
        acc[0] = fmaf(pa.x, v, acc[0]);
        acc[1] = fmaf(pa.y, v, acc[1]);
        acc[2] = fmaf(pa.z, v, acc[2]);
        acc[3] = fmaf(pa.w, v, acc[3]);
        acc[4] = fmaf(pb.x, v, acc[4]);
        acc[5] = fmaf(pb.y, v, acc[5]);
        acc[6] = fmaf(pb.z, v, acc[6]);
        acc[7] = fmaf(pb.w, v, acc[7]);
    }

    #pragma unroll
    for (int q = 0; q < 8; q++)
        out[(size_t)(l0 + q) * CDIM + h * DH + lane] = acc[q];
}

// ---------------------------------------------------------------------------
extern "C" void kernel_launch(void* const* d_in, const int* in_sizes, int n_in,
                              void* d_out, int out_size)
{
    const float* x    = (const float*)d_in[0];
    const float* Wp   = (const float*)d_in[1];
    const float* bp   = (const float*)d_in[2];
    const float* Wqkv = (const float*)d_in[3];
    const float* bqkv = (const float*)d_in[4];
    const float* Wo   = (const float*)d_in[5];
    const float* bo   = (const float*)d_in[6];
    float* out = (float*)d_out;

    float *p_y, *p_qkv, *p_att;
    cudaGetSymbolAddress((void**)&p_y,   g_y);
    cudaGetSymbolAddress((void**)&p_qkv, g_qkv);
    cudaGetSymbolAddress((void**)&p_att, g_att);

    const int natten_smem = (127 * RS * 2 + TQ * RS + 8 * PTROWS * PTS) * 4;
    static bool attr_set = false;
    if (!attr_set) {
        cudaFuncSetAttribute(natten_kernel,
                             cudaFuncAttributeMaxDynamicSharedMemorySize,
                             natten_smem);
        attr_set = true;
    }

    gemm_tf32_kernel<<<dim3(CDIM / 64, LSEQ / 128), 256>>>(
        x, Wp, bp, p_y, LSEQ, CDIM, FIN);

    gemm_tf32_kernel<<<dim3(C3 / 64, LSEQ / 128), 256>>>(
        p_y, Wqkv, bqkv, p_qkv, LSEQ, C3, CDIM);

    natten_kernel<<<dim3(LSEQ / TQ, NH), 256, natten_smem>>>(p_qkv, p_att);

    gemm_tf32_kernel<<<dim3(CDIM / 64, LSEQ / 128), 256>>>(
        p_att, Wo, bo, out, LSEQ, CDIM, CDIM);
}